// round 13
// baseline (speedup 1.0000x reference)
#include <cuda_runtime.h>
#include <cuda_fp16.h>
#include <math.h>
#include <float.h>
#include <stdint.h>

// Problem constants
#define N_TOK  16384          // B*S
#define HID    1024
#define GV     640            // NUM_GROUPS*NUM_VARS
#define NV     320            // NUM_VARS
#define CVD    128            // CODEVECTOR_DIM / NUM_GROUPS
#define KP     (HID / 2)      // 512 k-pairs

#define NWARPS_EP 8192        // epilogue: total warps (1024 blocks x 8 warps)
#define ROWS_PER_WARP 4       // 32768 rows / 8192 warps

// Scratch (static device globals; no allocation allowed)
__device__ float g_logits[(size_t)N_TOK * GV];          // 40 MB
__device__ float g_partial[(size_t)NWARPS_EP * NV];     // 10.5 MB
__device__ float g_marg[GV];
__device__ uint2 g_Ai[(size_t)N_TOK * KP];              // 64 MB: [row][kp] {hi2,lo2}
__device__ uint2 g_Bt[(size_t)KP * GV];                 // 2.5 MB: [kp][n]  {hi2,lo2}, x4096

#define B_SCALE   4096.0f
#define B_UNSCALE (1.0f / 4096.0f)

// ===========================================================================
// split helpers
// ===========================================================================
__device__ __forceinline__ uint32_t pack_h2(__half lo, __half hi) {
    __half2 p = __halves2half2(lo, hi);   // lo -> bits[0:16]
    return *reinterpret_cast<uint32_t*>(&p);
}
__device__ __forceinline__ uint2 split2(float x, float y) {
    __half hx = __float2half_rn(x), hy = __float2half_rn(y);
    float rx = x - __half2float(hx), ry = y - __half2float(hy);
    uint2 d;
    d.x = pack_h2(hx, hy);
    d.y = pack_h2(__float2half_rn(rx), __float2half_rn(ry));
    return d;
}

// ===========================================================================
// Kernel 0: pre-split A -> g_Ai ([row][kp]) and B*4096 -> g_Bt ([kp][n]).
// ===========================================================================
#define A_PAIRS ((size_t)N_TOK * KP)     // 8388608
#define B_PAIRS ((size_t)KP * GV)        // 327680
#define PS_THREADS 256

__global__ void presplit_kernel(const float* __restrict__ A,
                                const float* __restrict__ B)
{
    const size_t i = (size_t)blockIdx.x * PS_THREADS + threadIdx.x;
    if (i < A_PAIRS) {
        const float2 v = *reinterpret_cast<const float2*>(A + 2 * i);
        g_Ai[i] = split2(v.x, v.y);
    } else if (i < A_PAIRS + B_PAIRS) {
        const size_t i2 = i - A_PAIRS;       // = kp*GV + n  (write-coalesced)
        const int n  = (int)(i2 % GV);
        const int kp = (int)(i2 / GV);
        const float2 v = *reinterpret_cast<const float2*>(B + (size_t)n * HID + 2 * kp);
        g_Bt[i2] = split2(v.x * B_SCALE, v.y * B_SCALE);
    }
}

// ===========================================================================
// Kernel 1: FP16 3-term split GEMM via mma.sync.m16n8k16, cp.async fills.
// Block tile 128x64, 8 warps (4m x 2n), warp tile 32x32. BK=16.
// 3-stage cp.async ring, ONE __syncthreads per chunk. 1280 CTAs, 3/SM.
// ===========================================================================
#define BM 128
#define BN 64
#define BK 16
#define AP2 12      // A row pitch in uint2 (8 data + 4 pad)
#define BP2 68      // B kp-row pitch in uint2 (64 + 4 pad)
#define SZ_A2 (BM * AP2)        // 1536 uint2
#define SZ_B2 (8 * BP2)         // 544 uint2
#define STAGE2 (SZ_A2 + SZ_B2)  // 2080 uint2 = 16640 B
#define NSTAGE 3
#define SMEM_GEMM (NSTAGE * STAGE2 * 8)   // 49920 B (dynamic)

__device__ __forceinline__ void mma_f16(float c[4], const uint32_t a[4],
                                        const uint32_t b[2]) {
    asm volatile(
        "mma.sync.aligned.m16n8k16.row.col.f32.f16.f16.f32 "
        "{%0,%1,%2,%3}, {%4,%5,%6,%7}, {%8,%9}, {%0,%1,%2,%3};"
        : "+f"(c[0]), "+f"(c[1]), "+f"(c[2]), "+f"(c[3])
        : "r"(a[0]), "r"(a[1]), "r"(a[2]), "r"(a[3]), "r"(b[0]), "r"(b[1]));
}

#define CP16(dst32, src) \
    asm volatile("cp.async.cg.shared.global [%0], [%1], 16;" \
                 :: "r"(dst32), "l"(src))
#define CP_COMMIT() asm volatile("cp.async.commit_group;" ::: "memory")
#define CP_WAIT1()  asm volatile("cp.async.wait_group 1;" ::: "memory")
#define CP_WAIT0()  asm volatile("cp.async.wait_group 0;" ::: "memory")

__global__ __launch_bounds__(256, 3)
void gemm_f16x3_kernel(const float* __restrict__ bias)
{
    extern __shared__ uint2 S2d[];

    const int tid  = threadIdx.x;
    const int wid  = tid >> 5;
    const int lane = tid & 31;
    const int gid  = lane >> 2;         // 0..7
    const int tig  = lane & 3;          // 0..3
    const int wm   = (wid & 3) * 32;    // 4 m-warps
    const int wn   = (wid >> 2) * 32;   // 2 n-warps
    const int n0   = blockIdx.x * BN;
    const int m0   = blockIdx.y * BM;

    // cp.async slot geometry (16B chunks): A 512 slots, B 256 slots, 3/thread
    const int arow0 = tid >> 2, ajq = tid & 3;
    const int arow1 = arow0 + 64;
    const int kpl = tid >> 5, npos = tid & 31;   // B: kp-local 0..7, 16B pos 0..31

    uint32_t sb0;
    asm("{ .reg .u64 t; cvta.to.shared.u64 t, %1; cvt.u32.u64 %0, t; }"
        : "=r"(sb0) : "l"((const void*)S2d));
    const uint32_t dA0_off = (uint32_t)(arow0 * AP2 + ajq * 2) * 8;
    const uint32_t dA1_off = (uint32_t)(arow1 * AP2 + ajq * 2) * 8;
    const uint32_t dB_off  = (uint32_t)(SZ_A2 + kpl * BP2 + npos * 2) * 8;

    const uint2* Asrc0 = g_Ai + (size_t)(m0 + arow0) * KP + ajq * 2;
    const uint2* Asrc1 = g_Ai + (size_t)(m0 + arow1) * KP + ajq * 2;
    const uint2* Bsrc  = g_Bt + (size_t)kpl * GV + n0 + npos * 2;

#define ISSUE(CH, ST) do {                                                   \
        const uint32_t _b = sb0 + (uint32_t)(ST) * (STAGE2 * 8);             \
        CP16(_b + dA0_off, Asrc0 + (CH) * 8);                                \
        CP16(_b + dA1_off, Asrc1 + (CH) * 8);                                \
        CP16(_b + dB_off,  Bsrc  + (size_t)(CH) * 8 * GV);                   \
    } while (0)

    float c[2][4][4];
#pragma unroll
    for (int mt = 0; mt < 2; mt++)
#pragma unroll
        for (int j = 0; j < 4; j++)
#pragma unroll
            for (int q = 0; q < 4; q++) c[mt][j][q] = 0.f;

    // prologue: two chunks in flight
    ISSUE(0, 0); CP_COMMIT();
    ISSUE(1, 1); CP_COMMIT();

    int st = 0;      // stage of current chunk
#pragma unroll 1
    for (int chunk = 0; chunk < HID / BK; chunk++) {
        if (chunk < HID / BK - 1) CP_WAIT1(); else CP_WAIT0();
        __syncthreads();   // single barrier: data for `chunk` visible to all
                           // warps AND stage (chunk+2)%3 fully consumed

        if (chunk + 2 < HID / BK) {
            const int st2 = (st + 2 >= NSTAGE) ? (st + 2 - NSTAGE) : (st + 2);
            ISSUE(chunk + 2, st2);
            CP_COMMIT();
        }

        const uint2* SA = S2d + st * STAGE2;
        const uint2* SB = SA + SZ_A2;

        // A fragments (hi+lo in one LDS.64 each)
        uint32_t aH[2][4], aL[2][4];
#pragma unroll
        for (int mt = 0; mt < 2; mt++) {
            const int row = wm + mt * 16 + gid;
            const uint2 p0 = SA[row * AP2 + tig];
            const uint2 p1 = SA[(row + 8) * AP2 + tig];
            const uint2 p2 = SA[row * AP2 + tig + 4];
            const uint2 p3 = SA[(row + 8) * AP2 + tig + 4];
            aH[mt][0] = p0.x; aH[mt][1] = p1.x; aH[mt][2] = p2.x; aH[mt][3] = p3.x;
            aL[mt][0] = p0.y; aL[mt][1] = p1.y; aL[mt][2] = p2.y; aL[mt][3] = p3.y;
        }

        uint32_t bH[4][2], bL[4][2];
#pragma unroll
        for (int j4 = 0; j4 < 4; j4++) {
            const int col = wn + j4 * 8 + gid;
            const uint2 q0 = SB[tig * BP2 + col];
            const uint2 q1 = SB[(tig + 4) * BP2 + col];
            bH[j4][0] = q0.x; bH[j4][1] = q1.x;
            bL[j4][0] = q0.y; bL[j4][1] = q1.y;
        }
#pragma unroll
        for (int mt = 0; mt < 2; mt++)
#pragma unroll
            for (int j4 = 0; j4 < 4; j4++) {
                float* cc = c[mt][j4];
                mma_f16(cc, aH[mt], bH[j4]);   // hh
                mma_f16(cc, aL[mt], bH[j4]);   // lh
                mma_f16(cc, aH[mt], bL[j4]);   // hl
            }

        st = (st + 1 >= NSTAGE) ? 0 : (st + 1);
    }

    // epilogue: unscale, add bias, write logits
#pragma unroll
    for (int mt = 0; mt < 2; mt++) {
        const int row = m0 + wm + mt * 16 + gid;
#pragma unroll
        for (int j = 0; j < 4; j++) {
            const int col = n0 + wn + j * 8 + tig * 2;
            const float b0 = bias[col], b1 = bias[col + 1];
            float2 o0 = make_float2(fmaf(c[mt][j][0], B_UNSCALE, b0),
                                    fmaf(c[mt][j][1], B_UNSCALE, b1));
            float2 o1 = make_float2(fmaf(c[mt][j][2], B_UNSCALE, b0),
                                    fmaf(c[mt][j][3], B_UNSCALE, b1));
            *reinterpret_cast<float2*>(g_logits + (size_t)row * GV + col) = o0;
            *reinterpret_cast<float2*>(g_logits + (size_t)(row + 8) * GV + col) = o1;
        }
    }
}

// ===========================================================================
// Kernel 2: warp-per-row epilogue: gumbel argmax + gather + softmax marginal.
// 1024 blocks x 256 threads = 8192 warps; warp w handles rows w, w+8192, ...
// ===========================================================================
__device__ __forceinline__ unsigned long long pack_key(float z, int v)
{
    unsigned int b = __float_as_uint(z);
    b = (b & 0x80000000u) ? ~b : (b | 0x80000000u);   // order-preserving map
    return ((unsigned long long)b << 32) | (unsigned int)(0xFFFFFFFFu - (unsigned)v);
}

__global__ __launch_bounds__(256)
void epilogue_kernel(const float* __restrict__ u,
                     const float* __restrict__ cv,
                     float* __restrict__ out)
{
    const int lane = threadIdx.x & 31;
    const int w    = blockIdx.x * 8 + (threadIdx.x >> 5);   // 0..8191
    const int g    = w & 1;

    float marg[10];
#pragma unroll
    for (int i = 0; i < 10; i++) marg[i] = 0.f;

#pragma unroll 1
    for (int j = 0; j < ROWS_PER_WARP; j++) {
        const int r   = w + j * NWARPS_EP;
        const int tok = r >> 1;
        const float* lrow = g_logits + (size_t)tok * GV + g * NV;
        const float* urow = u + (size_t)r * NV;

        float l[10];
        unsigned long long key = 0;
        float m = -FLT_MAX;
#pragma unroll
        for (int i = 0; i < 10; i++) {
            const int v = lane + i * 32;
            const float li = lrow[v];
            // accurate logs: argmax flips are catastrophic
            const float zi = li - logf(-logf(urow[v]));
            const unsigned long long k = pack_key(zi, v);
            if (k > key) key = k;
            m = fmaxf(m, li);
            l[i] = li;
        }
#pragma unroll
        for (int o = 16; o > 0; o >>= 1) {
            m = fmaxf(m, __shfl_xor_sync(0xFFFFFFFFu, m, o));
            const unsigned long long ok = __shfl_xor_sync(0xFFFFFFFFu, key, o);
            if (ok > key) key = ok;
        }
        float e[10], s = 0.f;
#pragma unroll
        for (int i = 0; i < 10; i++) { e[i] = __expf(l[i] - m); s += e[i]; }
#pragma unroll
        for (int o = 16; o > 0; o >>= 1) s += __shfl_xor_sync(0xFFFFFFFFu, s, o);
        const float inv = __fdividef(1.f, s);
#pragma unroll
        for (int i = 0; i < 10; i++) marg[i] += e[i] * inv;

        const int idx = (int)(0xFFFFFFFFu - (unsigned int)(key & 0xFFFFFFFFull));
        const float4 vv = *reinterpret_cast<const float4*>(
            cv + ((size_t)(g * NV + idx)) * CVD + lane * 4);
        *reinterpret_cast<float4*>(out + (size_t)tok * 256 + g * CVD + lane * 4) = vv;
    }

#pragma unroll
    for (int i = 0; i < 10; i++)
        g_partial[(size_t)w * NV + lane + i * 32] = marg[i];
}

// ===========================================================================
// Kernel 3a: parallel deterministic reduce of partials -> marginal[640].
// ===========================================================================
__global__ void reduce_marg_kernel()
{
    const int b = blockIdx.x;           // 0..639 -> j = g*NV + v
    const int g = b / NV;
    const int v = b - g * NV;
    const int t = threadIdx.x;

    float s = 0.f;
#pragma unroll
    for (int k = 0; k < 16; k++) {
        const int w = g + 2 * (t + 256 * k);
        s += g_partial[(size_t)w * NV + v];
    }
    __shared__ float red[256];
    red[t] = s;
    __syncthreads();
#pragma unroll
    for (int o = 128; o > 0; o >>= 1) {
        if (t < o) red[t] += red[t + o];
        __syncthreads();
    }
    if (t == 0) g_marg[b] = red[0] * (1.0f / (float)N_TOK);
}

// ===========================================================================
// Kernel 3b: finalize perplexity scalar.
// ===========================================================================
__global__ void perplex_kernel(float* __restrict__ out, int out_size)
{
    const int tid = threadIdx.x;   // 640 threads
    __shared__ float sm[GV];
    const float m = g_marg[tid];
    sm[tid] = m * logf(m + 1e-7f);
    __syncthreads();
    if (tid == 0) {
        float s0 = 0.f, s1 = 0.f;
        for (int i = 0; i < NV; i++) { s0 += sm[i]; s1 += sm[NV + i]; }
        const float perp = expf(-s0) + expf(-s1);
        if (out_size > N_TOK * 256) out[(size_t)N_TOK * 256] = perp;
    }
}

// ===========================================================================
extern "C" void kernel_launch(void* const* d_in, const int* in_sizes, int n_in,
                              void* d_out, int out_size)
{
    const float* hs = (const float*)d_in[0];   // [16384,1024]
    const float* W  = (const float*)d_in[1];   // [640,1024]
    const float* b  = (const float*)d_in[2];   // [640]
    const float* cv = (const float*)d_in[3];   // [640,128]
    const float* gu = (const float*)d_in[4];   // [32768,320]
    float* out = (float*)d_out;

    cudaFuncSetAttribute(gemm_f16x3_kernel,
                         cudaFuncAttributeMaxDynamicSharedMemorySize, SMEM_GEMM);

    const int ps_blocks = (int)((A_PAIRS + B_PAIRS + PS_THREADS - 1) / PS_THREADS);
    presplit_kernel<<<ps_blocks, PS_THREADS>>>(hs, W);
    gemm_f16x3_kernel<<<dim3(GV / BN, N_TOK / BM), 256, SMEM_GEMM>>>(b);
    epilogue_kernel<<<1024, 256>>>(gu, cv, out);
    reduce_marg_kernel<<<GV, 256>>>();
    perplex_kernel<<<1, GV>>>(out, out_size);
}

// round 15
// speedup vs baseline: 1.0119x; 1.0119x over previous
#include <cuda_runtime.h>
#include <cuda_fp16.h>
#include <math.h>
#include <float.h>
#include <stdint.h>

// Problem constants
#define N_TOK  16384          // B*S
#define HID    1024
#define GV     640            // NUM_GROUPS*NUM_VARS
#define NV     320            // NUM_VARS
#define CVD    128            // CODEVECTOR_DIM / NUM_GROUPS
#define KP     (HID / 2)      // 512 k-pairs

#define NWARPS_EP 4096        // epilogue: total warps (512 blocks x 8 warps)
#define ROWS_PER_WARP 8       // 32768 rows / 4096 warps

// Scratch (static device globals; no allocation allowed)
__device__ float g_logits[(size_t)N_TOK * GV];          // 40 MB
__device__ float g_partial[(size_t)NWARPS_EP * NV];     // 5.2 MB
__device__ float g_marg[GV];
__device__ uint2 g_Ai[(size_t)N_TOK * KP];              // 64 MB: [row][kp] {hi2,lo2}
__device__ uint2 g_Bt[(size_t)KP * GV];                 // 2.5 MB: [kp][n]  {hi2,lo2}, x4096

#define B_SCALE   4096.0f
#define B_UNSCALE (1.0f / 4096.0f)

// ===========================================================================
// split helpers
// ===========================================================================
__device__ __forceinline__ uint32_t pack_h2(__half lo, __half hi) {
    __half2 p = __halves2half2(lo, hi);   // lo -> bits[0:16]
    return *reinterpret_cast<uint32_t*>(&p);
}
__device__ __forceinline__ uint2 split2(float x, float y) {
    __half hx = __float2half_rn(x), hy = __float2half_rn(y);
    float rx = x - __half2float(hx), ry = y - __half2float(hy);
    uint2 d;
    d.x = pack_h2(hx, hy);
    d.y = pack_h2(__float2half_rn(rx), __float2half_rn(ry));
    return d;
}

// ===========================================================================
// Kernel 0: pre-split A -> g_Ai ([row][kp]) and B*4096 -> g_Bt ([kp][n]).
// ===========================================================================
#define A_PAIRS ((size_t)N_TOK * KP)     // 8388608
#define B_PAIRS ((size_t)KP * GV)        // 327680
#define PS_THREADS 256

__global__ void presplit_kernel(const float* __restrict__ A,
                                const float* __restrict__ B)
{
    const size_t i = (size_t)blockIdx.x * PS_THREADS + threadIdx.x;
    if (i < A_PAIRS) {
        const float2 v = *reinterpret_cast<const float2*>(A + 2 * i);
        g_Ai[i] = split2(v.x, v.y);
    } else if (i < A_PAIRS + B_PAIRS) {
        const size_t i2 = i - A_PAIRS;       // = kp*GV + n  (write-coalesced)
        const int n  = (int)(i2 % GV);
        const int kp = (int)(i2 / GV);
        const float2 v = *reinterpret_cast<const float2*>(B + (size_t)n * HID + 2 * kp);
        g_Bt[i2] = split2(v.x * B_SCALE, v.y * B_SCALE);
    }
}

// ===========================================================================
// Kernel 1: FP16 3-term split GEMM via mma.sync.m16n8k16, cp.async fills.
// Block tile 128x64, 8 warps (4m x 2n), warp tile 32x32.
// BK=32 chunks (two k16 sub-steps per chunk), 2 stages, 1280 CTAs, 3/SM.
// ===========================================================================
#define BM 128
#define BN 64
#define BK 32
#define NCH (HID / BK)          // 32 chunks
#define AP2 12      // A row pitch in uint2 (8 data + 4 pad), per sub-chunk
#define BP2 68      // B kp-row pitch in uint2 (64 + 4 pad), per sub-chunk
#define SZ_A2 (BM * AP2)          // 1536 uint2
#define SZ_B2 (8 * BP2)           // 544 uint2
#define SUB2  (SZ_A2 + SZ_B2)     // 2080 uint2 = 16640 B per k16 sub-chunk
#define STAGE2 (2 * SUB2)         // 4160 uint2 = 33280 B per BK=32 stage
#define SMEM_GEMM (2 * STAGE2 * 8)  // 66560 B dynamic

__device__ __forceinline__ void mma_f16(float c[4], const uint32_t a[4],
                                        const uint32_t b[2]) {
    asm volatile(
        "mma.sync.aligned.m16n8k16.row.col.f32.f16.f16.f32 "
        "{%0,%1,%2,%3}, {%4,%5,%6,%7}, {%8,%9}, {%0,%1,%2,%3};"
        : "+f"(c[0]), "+f"(c[1]), "+f"(c[2]), "+f"(c[3])
        : "r"(a[0]), "r"(a[1]), "r"(a[2]), "r"(a[3]), "r"(b[0]), "r"(b[1]));
}

#define CP16(dst32, src) \
    asm volatile("cp.async.cg.shared.global [%0], [%1], 16;" \
                 :: "r"(dst32), "l"(src))
#define CP_COMMIT() asm volatile("cp.async.commit_group;" ::: "memory")
#define CP_WAIT1()  asm volatile("cp.async.wait_group 1;" ::: "memory")
#define CP_WAIT0()  asm volatile("cp.async.wait_group 0;" ::: "memory")

__global__ __launch_bounds__(256, 3)
void gemm_f16x3_kernel(const float* __restrict__ bias)
{
    extern __shared__ uint2 S2d[];

    const int tid  = threadIdx.x;
    const int wid  = tid >> 5;
    const int lane = tid & 31;
    const int gid  = lane >> 2;         // 0..7
    const int tig  = lane & 3;          // 0..3
    const int wm   = (wid & 3) * 32;    // 4 m-warps
    const int wn   = (wid >> 2) * 32;   // 2 n-warps
    const int n0   = blockIdx.x * BN;
    const int m0   = blockIdx.y * BM;

    // cp.async slot geometry per k16 sub-chunk (16B chunks):
    // A 512 slots (2/thread), B 256 slots (1/thread)
    const int arow0 = tid >> 2, ajq = tid & 3;
    const int arow1 = arow0 + 64;
    const int kpl = tid >> 5, npos = tid & 31;

    uint32_t sb0;
    asm("{ .reg .u64 t; cvta.to.shared.u64 t, %1; cvt.u32.u64 %0, t; }"
        : "=r"(sb0) : "l"((const void*)S2d));
    const uint32_t dA0_off = (uint32_t)(arow0 * AP2 + ajq * 2) * 8;
    const uint32_t dA1_off = (uint32_t)(arow1 * AP2 + ajq * 2) * 8;
    const uint32_t dB_off  = (uint32_t)(SZ_A2 + kpl * BP2 + npos * 2) * 8;

    const uint2* Asrc0 = g_Ai + (size_t)(m0 + arow0) * KP + ajq * 2;
    const uint2* Asrc1 = g_Ai + (size_t)(m0 + arow1) * KP + ajq * 2;
    const uint2* Bsrc  = g_Bt + (size_t)kpl * GV + n0 + npos * 2;

    // chunk CH covers kp [CH*16, CH*16+16); sub s covers kp [CH*16+s*8, +8)
#define ISSUE(CH, ST) do {                                                   \
        const uint32_t _b = sb0 + (uint32_t)(ST) * (STAGE2 * 8);             \
        _Pragma("unroll")                                                    \
        for (int _s = 0; _s < 2; _s++) {                                     \
            const uint32_t _bs = _b + (uint32_t)_s * (SUB2 * 8);             \
            const int _kp = (CH) * 16 + _s * 8;                              \
            CP16(_bs + dA0_off, Asrc0 + _kp);                                \
            CP16(_bs + dA1_off, Asrc1 + _kp);                                \
            CP16(_bs + dB_off,  Bsrc  + (size_t)_kp * GV);                   \
        }                                                                    \
    } while (0)

    float c[2][4][4];
#pragma unroll
    for (int mt = 0; mt < 2; mt++)
#pragma unroll
        for (int j = 0; j < 4; j++)
#pragma unroll
            for (int q = 0; q < 4; q++) c[mt][j][q] = 0.f;

    // prologue
    ISSUE(0, 0);
    CP_COMMIT();

    int buf = 0;
#pragma unroll 1
    for (int chunk = 0; chunk < NCH; chunk++) {
        const bool more = (chunk < NCH - 1);
        if (more) {
            ISSUE(chunk + 1, buf ^ 1);
            CP_COMMIT();
            CP_WAIT1();
        } else {
            CP_WAIT0();
        }
        __syncthreads();

#pragma unroll
        for (int s = 0; s < 2; s++) {
            const uint2* SA = S2d + buf * STAGE2 + s * SUB2;
            const uint2* SB = SA + SZ_A2;

            // A fragments (hi+lo in one LDS.64 each)
            uint32_t aH[2][4], aL[2][4];
#pragma unroll
            for (int mt = 0; mt < 2; mt++) {
                const int row = wm + mt * 16 + gid;
                const uint2 p0 = SA[row * AP2 + tig];
                const uint2 p1 = SA[(row + 8) * AP2 + tig];
                const uint2 p2 = SA[row * AP2 + tig + 4];
                const uint2 p3 = SA[(row + 8) * AP2 + tig + 4];
                aH[mt][0] = p0.x; aH[mt][1] = p1.x; aH[mt][2] = p2.x; aH[mt][3] = p3.x;
                aL[mt][0] = p0.y; aL[mt][1] = p1.y; aL[mt][2] = p2.y; aL[mt][3] = p3.y;
            }

            uint32_t bH[4][2], bL[4][2];
#pragma unroll
            for (int j4 = 0; j4 < 4; j4++) {
                const int col = wn + j4 * 8 + gid;
                const uint2 q0 = SB[tig * BP2 + col];
                const uint2 q1 = SB[(tig + 4) * BP2 + col];
                bH[j4][0] = q0.x; bH[j4][1] = q1.x;
                bL[j4][0] = q0.y; bL[j4][1] = q1.y;
            }
#pragma unroll
            for (int mt = 0; mt < 2; mt++)
#pragma unroll
                for (int j4 = 0; j4 < 4; j4++) {
                    float* cc = c[mt][j4];
                    mma_f16(cc, aH[mt], bH[j4]);   // hh
                    mma_f16(cc, aL[mt], bH[j4]);   // lh
                    mma_f16(cc, aH[mt], bL[j4]);   // hl
                }
        }

        __syncthreads();   // all warps done with S2d[buf] before refill
        buf ^= 1;
    }

    // epilogue: unscale, add bias, write logits
#pragma unroll
    for (int mt = 0; mt < 2; mt++) {
        const int row = m0 + wm + mt * 16 + gid;
#pragma unroll
        for (int j = 0; j < 4; j++) {
            const int col = n0 + wn + j * 8 + tig * 2;
            const float b0 = bias[col], b1 = bias[col + 1];
            float2 o0 = make_float2(fmaf(c[mt][j][0], B_UNSCALE, b0),
                                    fmaf(c[mt][j][1], B_UNSCALE, b1));
            float2 o1 = make_float2(fmaf(c[mt][j][2], B_UNSCALE, b0),
                                    fmaf(c[mt][j][3], B_UNSCALE, b1));
            *reinterpret_cast<float2*>(g_logits + (size_t)row * GV + col) = o0;
            *reinterpret_cast<float2*>(g_logits + (size_t)(row + 8) * GV + col) = o1;
        }
    }
}

// ===========================================================================
// Kernel 2: warp-per-row epilogue: gumbel argmax + gather + softmax marginal.
// 512 blocks x 256 threads = 4096 warps; warp w handles rows w, w+4096, ...
// ===========================================================================
__device__ __forceinline__ unsigned long long pack_key(float z, int v)
{
    unsigned int b = __float_as_uint(z);
    b = (b & 0x80000000u) ? ~b : (b | 0x80000000u);   // order-preserving map
    return ((unsigned long long)b << 32) | (unsigned int)(0xFFFFFFFFu - (unsigned)v);
}

__global__ __launch_bounds__(256)
void epilogue_kernel(const float* __restrict__ u,
                     const float* __restrict__ cv,
                     float* __restrict__ out)
{
    const int lane = threadIdx.x & 31;
    const int w    = blockIdx.x * 8 + (threadIdx.x >> 5);   // 0..4095
    const int g    = w & 1;

    float marg[10];
#pragma unroll
    for (int i = 0; i < 10; i++) marg[i] = 0.f;

#pragma unroll 1
    for (int j = 0; j < ROWS_PER_WARP; j++) {
        const int r   = w + j * NWARPS_EP;
        const int tok = r >> 1;
        const float* lrow = g_logits + (size_t)tok * GV + g * NV;
        const float* urow = u + (size_t)r * NV;

        float l[10];
        unsigned long long key = 0;
        float m = -FLT_MAX;
#pragma unroll
        for (int i = 0; i < 10; i++) {
            const int v = lane + i * 32;
            const float li = lrow[v];
            // accurate logs: argmax flips are catastrophic
            const float zi = li - logf(-logf(urow[v]));
            const unsigned long long k = pack_key(zi, v);
            if (k > key) key = k;
            m = fmaxf(m, li);
            l[i] = li;
        }
#pragma unroll
        for (int o = 16; o > 0; o >>= 1) {
            m = fmaxf(m, __shfl_xor_sync(0xFFFFFFFFu, m, o));
            const unsigned long long ok = __shfl_xor_sync(0xFFFFFFFFu, key, o);
            if (ok > key) key = ok;
        }
        float e[10], s = 0.f;
#pragma unroll
        for (int i = 0; i < 10; i++) { e[i] = __expf(l[i] - m); s += e[i]; }
#pragma unroll
        for (int o = 16; o > 0; o >>= 1) s += __shfl_xor_sync(0xFFFFFFFFu, s, o);
        const float inv = __fdividef(1.f, s);
#pragma unroll
        for (int i = 0; i < 10; i++) marg[i] += e[i] * inv;

        const int idx = (int)(0xFFFFFFFFu - (unsigned int)(key & 0xFFFFFFFFull));
        const float4 vv = *reinterpret_cast<const float4*>(
            cv + ((size_t)(g * NV + idx)) * CVD + lane * 4);
        *reinterpret_cast<float4*>(out + (size_t)tok * 256 + g * CVD + lane * 4) = vv;
    }

#pragma unroll
    for (int i = 0; i < 10; i++)
        g_partial[(size_t)w * NV + lane + i * 32] = marg[i];
}

// ===========================================================================
// Kernel 3a: parallel deterministic reduce of partials -> marginal[640].
// ===========================================================================
__global__ void reduce_marg_kernel()
{
    const int b = blockIdx.x;           // 0..639 -> j = g*NV + v
    const int g = b / NV;
    const int v = b - g * NV;
    const int t = threadIdx.x;

    float s = 0.f;
#pragma unroll
    for (int k = 0; k < 8; k++) {
        const int w = g + 2 * (t + 256 * k);
        s += g_partial[(size_t)w * NV + v];
    }
    __shared__ float red[256];
    red[t] = s;
    __syncthreads();
#pragma unroll
    for (int o = 128; o > 0; o >>= 1) {
        if (t < o) red[t] += red[t + o];
        __syncthreads();
    }
    if (t == 0) g_marg[b] = red[0] * (1.0f / (float)N_TOK);
}

// ===========================================================================
// Kernel 3b: finalize perplexity scalar.
// ===========================================================================
__global__ void perplex_kernel(float* __restrict__ out, int out_size)
{
    const int tid = threadIdx.x;   // 640 threads
    __shared__ float sm[GV];
    const float m = g_marg[tid];
    sm[tid] = m * logf(m + 1e-7f);
    __syncthreads();
    if (tid == 0) {
        float s0 = 0.f, s1 = 0.f;
        for (int i = 0; i < NV; i++) { s0 += sm[i]; s1 += sm[NV + i]; }
        const float perp = expf(-s0) + expf(-s1);
        if (out_size > N_TOK * 256) out[(size_t)N_TOK * 256] = perp;
    }
}

// ===========================================================================
extern "C" void kernel_launch(void* const* d_in, const int* in_sizes, int n_in,
                              void* d_out, int out_size)
{
    const float* hs = (const float*)d_in[0];   // [16384,1024]
    const float* W  = (const float*)d_in[1];   // [640,1024]
    const float* b  = (const float*)d_in[2];   // [640]
    const float* cv = (const float*)d_in[3];   // [640,128]
    const float* gu = (const float*)d_in[4];   // [32768,320]
    float* out = (float*)d_out;

    cudaFuncSetAttribute(gemm_f16x3_kernel,
                         cudaFuncAttributeMaxDynamicSharedMemorySize, SMEM_GEMM);

    const int ps_blocks = (int)((A_PAIRS + B_PAIRS + PS_THREADS - 1) / PS_THREADS);
    presplit_kernel<<<ps_blocks, PS_THREADS>>>(hs, W);
    gemm_f16x3_kernel<<<dim3(GV / BN, N_TOK / BM), 256, SMEM_GEMM>>>(b);
    epilogue_kernel<<<512, 256>>>(gu, cv, out);
    reduce_marg_kernel<<<GV, 256>>>();
    perplex_kernel<<<1, GV>>>(out, out_size);
}